// round 7
// baseline (speedup 1.0000x reference)
#include <cuda_runtime.h>

// B=8, MSP=2048, D=512, A=64, NB=5
// Exact contraction reordering:
//   Wc[n,d]   = W_fl[n,d] + W_fl[n,512+d]
//   S[n]      = sum_d Wc[n,d]
//   t[b,s,n]  = sum_d e[b,s,d] * Wc[n,d]     (stored transposed g_tT[n][b*MSP+s])
//   out[b,a,n]= sum_s W_ll[a,s] * t[b,s,n] + b_ll[a]*S[n] + b_fl[n]
//   final[b,i,j,n] = out[b,i,n]
//
// Single persistent kernel, 148 blocks (1/SM, all resident) x 256 threads.
// Software grid barriers via atomic counters (all blocks resident => safe).
// Counters and the partial-out table are reset by the last block each launch
// so every graph replay starts from the same state.

#define NROWS  16384
#define DVAL   512
#define NB     5
#define AVAL   64
#define BVAL   8
#define MSP    2048
#define GRID   148
#define TPB    256
#define NWARPS (GRID * 8)

__device__ int   g_done1, g_done2, g_done3;
__device__ float g_S[NB];
__device__ float g_tT[NB * NROWS];            // 320 KB, L2-resident
__device__ float g_out2[BVAL * AVAL * NB];    // 2560 floats, zero at launch entry

__device__ __forceinline__ void grid_barrier(int* ctr, int tid) {
    __threadfence();            // publish this thread's prior writes (gpu scope)
    __syncthreads();
    if (tid == 0) {
        atomicAdd(ctr, 1);
        while (atomicAdd(ctr, 0) < GRID) { }
    }
    __syncthreads();
}

__global__ __launch_bounds__(TPB) void fused_kernel(const float* __restrict__ e,
                                                    const float* __restrict__ W_fl,
                                                    const float* __restrict__ W_ll,
                                                    const float* __restrict__ b_ll,
                                                    const float* __restrict__ b_fl,
                                                    float* __restrict__ out) {
    __shared__ __align__(16) float wcs[NB * DVAL];   // 10 KB
    __shared__ int last;
    const int tid  = threadIdx.x;
    const int lane = tid & 31;
    const int warp = tid >> 5;

    // ---------------- Phase 1: t ----------------
    for (int i = tid; i < NB * DVAL; i += TPB) {
        int n = i / DVAL, d = i - n * DVAL;
        wcs[i] = W_fl[n * 1024 + d] + W_fl[n * 1024 + 512 + d];
    }
    __syncthreads();

    if (blockIdx.x == 0 && warp == 0) {
        #pragma unroll
        for (int n = 0; n < NB; n++) {
            float s = 0.f;
            for (int d = lane; d < DVAL; d += 32) s += wcs[n * DVAL + d];
            #pragma unroll
            for (int off = 16; off > 0; off >>= 1)
                s += __shfl_xor_sync(0xFFFFFFFFu, s, off);
            if (lane == 0) g_S[n] = s;
        }
    }

    // Per-lane Wc registers: lane owns d = r*128 + lane*4 .. +3
    float4 wc[4][NB];
    #pragma unroll
    for (int r = 0; r < 4; r++)
        #pragma unroll
        for (int n = 0; n < NB; n++)
            wc[r][n] = *(const float4*)&wcs[n * DVAL + r * 128 + lane * 4];

    const int gw = blockIdx.x * 8 + warp;

    int row = gw;
    float4 ev[4];
    if (row < NROWS) {
        const float4* er = (const float4*)(e + (size_t)row * DVAL);
        #pragma unroll
        for (int r = 0; r < 4; r++) ev[r] = er[r * 32 + lane];
    }
    while (row < NROWS) {
        const int nxt = row + NWARPS;
        float4 ev2[4];
        if (nxt < NROWS) {
            const float4* er2 = (const float4*)(e + (size_t)nxt * DVAL);
            #pragma unroll
            for (int r = 0; r < 4; r++) ev2[r] = er2[r * 32 + lane];
        }

        float acc[NB];
        #pragma unroll
        for (int n = 0; n < NB; n++) acc[n] = 0.f;
        #pragma unroll
        for (int r = 0; r < 4; r++) {
            #pragma unroll
            for (int n = 0; n < NB; n++) {
                acc[n] += ev[r].x * wc[r][n].x;
                acc[n] += ev[r].y * wc[r][n].y;
                acc[n] += ev[r].z * wc[r][n].z;
                acc[n] += ev[r].w * wc[r][n].w;
            }
        }
        #pragma unroll
        for (int n = 0; n < NB; n++) {
            #pragma unroll
            for (int off = 16; off > 0; off >>= 1)
                acc[n] += __shfl_xor_sync(0xFFFFFFFFu, acc[n], off);
        }
        if (lane < NB) {
            float v = (lane == 0) ? acc[0] : (lane == 1) ? acc[1] :
                      (lane == 2) ? acc[2] : (lane == 3) ? acc[3] : acc[4];
            g_tT[lane * NROWS + row] = v;
        }
        #pragma unroll
        for (int r = 0; r < 4; r++) ev[r] = ev2[r];
        row = nxt;
    }

    grid_barrier(&g_done1, tid);

    // ---------------- Phase 2: partial out ----------------
    // 1024 tasks = 512 (b,a) pairs x 2 s-halves; warp W handles task W.
    {
        const int W = gw;
        if (W < 1024) {
            const int pair  = W >> 1;
            const int half  = W & 1;
            const int b     = pair >> 6;
            const int a     = pair & 63;
            const int sbase = half * 1024;

            const float* wrow = W_ll + (size_t)a * MSP + sbase;
            const float* tp0  = g_tT + 0 * NROWS + (size_t)b * MSP + sbase;
            const float* tp1  = g_tT + 1 * NROWS + (size_t)b * MSP + sbase;
            const float* tp2  = g_tT + 2 * NROWS + (size_t)b * MSP + sbase;
            const float* tp3  = g_tT + 3 * NROWS + (size_t)b * MSP + sbase;
            const float* tp4  = g_tT + 4 * NROWS + (size_t)b * MSP + sbase;

            float a0 = 0.f, a1 = 0.f, a2 = 0.f, a3 = 0.f, a4 = 0.f;
            #pragma unroll 4
            for (int k = 0; k < 32; k++) {
                const int s = lane + 32 * k;
                const float wv = wrow[s];
                a0 += wv * tp0[s];
                a1 += wv * tp1[s];
                a2 += wv * tp2[s];
                a3 += wv * tp3[s];
                a4 += wv * tp4[s];
            }
            #pragma unroll
            for (int off = 16; off > 0; off >>= 1) {
                a0 += __shfl_xor_sync(0xFFFFFFFFu, a0, off);
                a1 += __shfl_xor_sync(0xFFFFFFFFu, a1, off);
                a2 += __shfl_xor_sync(0xFFFFFFFFu, a2, off);
                a3 += __shfl_xor_sync(0xFFFFFFFFu, a3, off);
                a4 += __shfl_xor_sync(0xFFFFFFFFu, a4, off);
            }
            if (lane == 0) {
                float* gp = &g_out2[pair * NB];
                atomicAdd(gp + 0, a0);
                atomicAdd(gp + 1, a1);
                atomicAdd(gp + 2, a2);
                atomicAdd(gp + 3, a3);
                atomicAdd(gp + 4, a4);
            }
        }
    }

    grid_barrier(&g_done2, tid);

    // ---------------- Phase 3: biases + broadcast ----------------
    {
        const int gtid = blockIdx.x * TPB + tid;
        for (int f = gtid; f < BVAL * AVAL * AVAL * NB; f += GRID * TPB) {
            const int n = f % NB;
            const int q = f / NB;              // (b*64 + i)*64 + j
            const int i = (q >> 6) & 63;
            const int b = q >> 12;
            out[f] = g_out2[(b * AVAL + i) * NB + n] + b_ll[i] * g_S[n] + b_fl[n];
        }
    }

    // ---------------- Completion: last block resets state ----------------
    __threadfence();
    __syncthreads();
    if (tid == 0) last = (atomicAdd(&g_done3, 1) == GRID - 1) ? 1 : 0;
    __syncthreads();
    if (last) {
        for (int i = tid; i < BVAL * AVAL * NB; i += TPB) g_out2[i] = 0.f;
        __syncthreads();
        if (tid == 0) {
            __threadfence();
            g_done1 = 0; g_done2 = 0; g_done3 = 0;
            __threadfence();
        }
    }
}

// ---------------------------------------------------------------------------
extern "C" void kernel_launch(void* const* d_in, const int* in_sizes, int n_in,
                              void* d_out, int out_size) {
    const float* e    = (const float*)d_in[0];
    const float* W_ll = (const float*)d_in[1];
    const float* b_ll = (const float*)d_in[2];
    const float* W_fl = (const float*)d_in[3];
    const float* b_fl = (const float*)d_in[4];
    float* out = (float*)d_out;

    fused_kernel<<<GRID, TPB>>>(e, W_fl, W_ll, b_ll, b_fl, out);
}

// round 8
// speedup vs baseline: 1.4239x; 1.4239x over previous
#include <cuda_runtime.h>

// B=8, MSP=2048, D=512, A=64, NB=5
// Exact contraction reordering:
//   Wc[n,d]   = W_fl[n,d] + W_fl[n,512+d]
//   S[n]      = sum_d Wc[n,d]
//   t[b,s,n]  = sum_d e[b,s,d] * Wc[n,d]
//   out[b,a,n]= sum_s W_ll[a,s] * t[b,s,n] + b_ll[a]*S[n] + b_fl[n]
//   final[b,i,j,n] = out[b,i,n]
//
// Kernel 1 fuses t and the s-contraction: each warp owns a contiguous s-chunk
// of one b, computes t[s,:] (FFMA2 + butterfly), and folds it into per-lane
// register accumulators for a=lane and a=lane+32. Block epilogue combines the
// 6 warps in smem and atomicAdds 320 partials into g_out2.
// Kernel 2 applies biases, broadcasts over j, and re-zeros g_out2 (each
// element has exactly one reader block -> safe per-replay reset).

#define DVAL   512
#define NB     5
#define AVAL   64
#define BVAL   8
#define MSP    2048
#define K1GRID 296
#define K1WPB  6              // warps per block
#define WPB_B  222            // warps per batch b (= 6 * 37)

__device__ float g_S[NB];
__device__ float g_out2[BVAL * AVAL * NB];   // 2560 floats, zero at launch entry

// Packed f32x2 FMA (Blackwell)
__device__ __forceinline__ unsigned long long fma2(unsigned long long a,
                                                   unsigned long long b,
                                                   unsigned long long c) {
    unsigned long long d;
    asm("fma.rn.f32x2 %0, %1, %2, %3;" : "=l"(d) : "l"(a), "l"(b), "l"(c));
    return d;
}
__device__ __forceinline__ float unpack_add(unsigned long long v) {
    float lo, hi;
    asm("mov.b64 {%0, %1}, %2;" : "=f"(lo), "=f"(hi) : "l"(v));
    return lo + hi;
}

// ---------------------------------------------------------------------------
// Kernel 1: fused t + a-contraction. 296 blocks x 192 threads (2/SM).
// ---------------------------------------------------------------------------
__global__ __launch_bounds__(192, 2) void fused_kernel(const float* __restrict__ e,
                                                       const float* __restrict__ W_fl,
                                                       const float* __restrict__ W_ll) {
    __shared__ __align__(16) float wcs[NB * DVAL];       // 10 KB
    __shared__ float sacc[K1WPB][AVAL * NB];             // 7.5 KB
    const int tid  = threadIdx.x;
    const int lane = tid & 31;
    const int warp = tid >> 5;

    // Build Wc in smem
    for (int i = tid; i < NB * DVAL; i += 192) {
        int n = i / DVAL, d = i - n * DVAL;
        wcs[i] = W_fl[n * 1024 + d] + W_fl[n * 1024 + 512 + d];
    }
    __syncthreads();

    if (blockIdx.x == 0 && warp == 0) {
        #pragma unroll
        for (int n = 0; n < NB; n++) {
            float s = 0.f;
            for (int d = lane; d < DVAL; d += 32) s += wcs[n * DVAL + d];
            #pragma unroll
            for (int off = 16; off > 0; off >>= 1)
                s += __shfl_xor_sync(0xFFFFFFFFu, s, off);
            if (lane == 0) g_S[n] = s;
        }
    }

    // Per-lane Wc as packed f32x2: lane owns d = r*128 + lane*4 .. +3
    ulonglong2 wc2[4][NB];
    #pragma unroll
    for (int r = 0; r < 4; r++)
        #pragma unroll
        for (int n = 0; n < NB; n++)
            wc2[r][n] = *(const ulonglong2*)&wcs[n * DVAL + r * 128 + lane * 4];

    // b-aligned work split: all 6 warps of a block share one b.
    const int b  = blockIdx.x / 37;                 // 37 blocks per b
    const int wi = blockIdx.x * K1WPB + warp - b * WPB_B;   // 0..221
    const int s0 = (wi * MSP) / WPB_B;
    const int s1 = ((wi + 1) * MSP) / WPB_B;        // 9-10 rows

    const float* wl0p = W_ll + (size_t)lane * MSP;
    const float* wl1p = W_ll + (size_t)(lane + 32) * MSP;
    const float* ebase = e + (size_t)b * MSP * DVAL;

    float accA0[NB], accA1[NB];
    #pragma unroll
    for (int n = 0; n < NB; n++) { accA0[n] = 0.f; accA1[n] = 0.f; }

    int s = s0;
    ulonglong2 ev[4];
    float wl0 = 0.f, wl1 = 0.f;
    if (s < s1) {
        const ulonglong2* er = (const ulonglong2*)(ebase + (size_t)s * DVAL);
        #pragma unroll
        for (int r = 0; r < 4; r++) ev[r] = er[r * 32 + lane];
        wl0 = wl0p[s]; wl1 = wl1p[s];
    }

    while (s < s1) {
        const int sn = s + 1;
        ulonglong2 ev2[4];
        float wl0n = 0.f, wl1n = 0.f;
        if (sn < s1) {
            const ulonglong2* er2 = (const ulonglong2*)(ebase + (size_t)sn * DVAL);
            #pragma unroll
            for (int r = 0; r < 4; r++) ev2[r] = er2[r * 32 + lane];
            wl0n = wl0p[sn]; wl1n = wl1p[sn];
        }

        unsigned long long acc2[NB];
        #pragma unroll
        for (int n = 0; n < NB; n++) acc2[n] = 0ull;
        #pragma unroll
        for (int r = 0; r < 4; r++) {
            #pragma unroll
            for (int n = 0; n < NB; n++) {
                acc2[n] = fma2(ev[r].x, wc2[r][n].x, acc2[n]);
                acc2[n] = fma2(ev[r].y, wc2[r][n].y, acc2[n]);
            }
        }

        float t[NB];
        #pragma unroll
        for (int n = 0; n < NB; n++) t[n] = unpack_add(acc2[n]);
        #pragma unroll
        for (int n = 0; n < NB; n++) {
            #pragma unroll
            for (int off = 16; off > 0; off >>= 1)
                t[n] += __shfl_xor_sync(0xFFFFFFFFu, t[n], off);
        }

        // Fold into register accumulators for a = lane and a = lane+32
        #pragma unroll
        for (int n = 0; n < NB; n++) {
            accA0[n] += wl0 * t[n];
            accA1[n] += wl1 * t[n];
        }

        #pragma unroll
        for (int r = 0; r < 4; r++) ev[r] = ev2[r];
        wl0 = wl0n; wl1 = wl1n;
        s = sn;
    }

    // Epilogue: combine 6 warps in smem, one atomicAdd per element per block
    {
        float* sp = sacc[warp];
        #pragma unroll
        for (int n = 0; n < NB; n++) {
            sp[lane * NB + n]        = accA0[n];
            sp[(lane + 32) * NB + n] = accA1[n];
        }
    }
    __syncthreads();
    for (int idx = tid; idx < AVAL * NB; idx += 192) {
        float sum = 0.f;
        #pragma unroll
        for (int w = 0; w < K1WPB; w++) sum += sacc[w][idx];
        atomicAdd(&g_out2[b * (AVAL * NB) + idx], sum);
    }
}

// ---------------------------------------------------------------------------
// Kernel 2: biases + broadcast + reset. grid = (64 i, 8 b), 128 threads.
// ---------------------------------------------------------------------------
__global__ __launch_bounds__(128) void bcast_kernel(const float* __restrict__ b_ll,
                                                    const float* __restrict__ b_fl,
                                                    float* __restrict__ out) {
    __shared__ float v[NB];
    __shared__ __align__(16) float pat[20];     // lcm(4,5) pattern
    const int i   = blockIdx.x;
    const int b   = blockIdx.y;
    const int tid = threadIdx.x;
    const int gi  = (b * AVAL + i) * NB;

    if (tid < NB)
        v[tid] = g_out2[gi + tid] + b_ll[i] * g_S[tid] + b_fl[tid];
    __syncthreads();

    if (tid < NB) g_out2[gi + tid] = 0.f;        // reset for next replay
    if (tid < 20) pat[tid] = v[tid % NB];
    __syncthreads();

    // 320 floats = 80 float4, repeating every 5 float4s
    float4* base = (float4*)(out + (size_t)(b * AVAL + i) * (AVAL * NB));
    if (tid < 80) base[tid] = ((const float4*)pat)[tid % NB];
}

// ---------------------------------------------------------------------------
extern "C" void kernel_launch(void* const* d_in, const int* in_sizes, int n_in,
                              void* d_out, int out_size) {
    const float* e    = (const float*)d_in[0];
    const float* W_ll = (const float*)d_in[1];
    const float* b_ll = (const float*)d_in[2];
    const float* W_fl = (const float*)d_in[3];
    const float* b_fl = (const float*)d_in[4];
    float* out = (float*)d_out;

    fused_kernel<<<K1GRID, 192>>>(e, W_fl, W_ll);
    bcast_kernel<<<dim3(AVAL, BVAL), 128>>>(b_ll, b_fl, out);
}